// round 6
// baseline (speedup 1.0000x reference)
#include <cuda_runtime.h>
#include <cuda_bf16.h>
#include <cstdint>
#include <cstddef>

#define SEQ 256
#define BATCH 32
#define IN_DIM 1024
#define HID 64
#define NM 8
#define NM1 9
#define ROWS (SEQ*BATCH)     /* 8192 */
#define NKV (NM1*HID)        /* 576  */
#define WROWS 1088           /* Wk slots0-7 (512) | Wv slots0-7 (512) | Wq (64) */
#define R512 512             /* u32 per row (1024 bf16) */

// ---------------- scratch (device globals; no allocation allowed) ----------------
__device__ uint32_t g_Xh[(size_t)ROWS * R512];     // bf16-hi, psi-permuted X
__device__ uint32_t g_Xl[(size_t)ROWS * R512];     // bf16-lo residual
__device__ uint32_t g_Wh[(size_t)WROWS * R512];
__device__ uint32_t g_Wl[(size_t)WROWS * R512];
__device__ float  g_Ck[(size_t)ROWS * NKV];
__device__ float  g_Cv[(size_t)ROWS * NKV];
__device__ float  g_Cq[(size_t)ROWS * HID];
__device__ int2   g_ri[ROWS];
__device__ int4   g_meta[ROWS];                    // {i0, i1, bits(g0), bits(g1)}
__device__ int    g_list[8][ROWS];
__device__ int    g_cnt[8];
__device__ float  g_c3[(size_t)ROWS * 3 * HID];    // compact contribs

// ---------------- helpers ----------------
__device__ __forceinline__ uint32_t smem_u32(const void* p) {
    uint32_t a;
    asm("{ .reg .u64 t; cvta.to.shared.u64 t, %1; cvt.u32.u64 %0, t; }" : "=r"(a) : "l"(p));
    return a;
}
__device__ __forceinline__ void cp16(uint32_t dst, const void* src) {
    asm volatile("cp.async.cg.shared.global [%0], [%1], 16;\n" :: "r"(dst), "l"(src) : "memory");
}
__device__ __forceinline__ void cp_commit() { asm volatile("cp.async.commit_group;\n" ::: "memory"); }
template<int N> __device__ __forceinline__ void cp_wait() {
    asm volatile("cp.async.wait_group %0;\n" :: "n"(N) : "memory");
}
// pack two floats to bf16x2: low half = even, high half = odd
__device__ __forceinline__ uint32_t bf2pack(float e, float o) {
    uint32_t u;
    asm("cvt.rn.bf16x2.f32 %0, %1, %2;" : "=r"(u) : "f"(o), "f"(e));
    return u;
}
__device__ __forceinline__ float bfres(float f) {
    return f - __bfloat162float(__float2bfloat16(f));
}
__device__ __forceinline__ void mma_bf16(float* d, const uint32_t* a, const uint32_t* b) {
    asm volatile(
        "mma.sync.aligned.m16n8k16.row.col.f32.bf16.bf16.f32 "
        "{%0,%1,%2,%3},{%4,%5,%6,%7},{%8,%9},{%0,%1,%2,%3};"
        : "+f"(d[0]), "+f"(d[1]), "+f"(d[2]), "+f"(d[3])
        : "r"(a[0]), "r"(a[1]), "r"(a[2]), "r"(a[3]), "r"(b[0]), "r"(b[1]));
}

// psi permute within a 16-col block: slot pairs
__constant__ int c_pr[8][2] = {{0,1},{8,9},{2,3},{10,11},{4,5},{12,13},{6,7},{14,15}};

// ---------------- weight prep: split+permute Wk(0..511)|Wv|Wq; zero g_cnt ----------------
__global__ __launch_bounds__(256) void prep_w(
    const float* __restrict__ Wk, const float* __restrict__ Wv,
    const float* __restrict__ Wq)
{
    if (blockIdx.x == 0 && threadIdx.x < 8) g_cnt[threadIdx.x] = 0;
    const int id = blockIdx.x * 256 + threadIdx.x;
    if (id >= WROWS * 64) return;
    const int row = id >> 6, blk = id & 63;
    const float* src;
    if (row < 512)       src = Wk + (size_t)row * IN_DIM;
    else if (row < 1024) src = Wv + (size_t)(row - 512) * IN_DIM;
    else                 src = Wq + (size_t)(row - 1024) * IN_DIM;

    float f[16];
    const float4* s4 = (const float4*)(src + blk * 16);
#pragma unroll
    for (int c = 0; c < 4; c++) {
        float4 v = s4[c];
        f[4 * c] = v.x; f[4 * c + 1] = v.y; f[4 * c + 2] = v.z; f[4 * c + 3] = v.w;
    }
    uint32_t hs[8], ls[8];
#pragma unroll
    for (int s = 0; s < 8; s++) {
        const float e = f[c_pr[s][0]], o = f[c_pr[s][1]];
        hs[s] = bf2pack(e, o);
        ls[s] = bf2pack(bfres(e), bfres(o));
    }
    const size_t base = (size_t)row * R512 + blk * 8;
    *(uint4*)(g_Wh + base)     = make_uint4(hs[0], hs[1], hs[2], hs[3]);
    *(uint4*)(g_Wh + base + 4) = make_uint4(hs[4], hs[5], hs[6], hs[7]);
    *(uint4*)(g_Wl + base)     = make_uint4(ls[0], ls[1], ls[2], ls[3]);
    *(uint4*)(g_Wl + base + 4) = make_uint4(ls[4], ls[5], ls[6], ls[7]);
}

// ---------------- gate: exact fp32 logits + softmax + top-2; writes split X ----------------
__global__ __launch_bounds__(256) void gate_kernel(
    const float* __restrict__ X, const float* __restrict__ Wg,
    const float* __restrict__ Wgb)
{
    const int wid  = blockIdx.x * 8 + (threadIdx.x >> 5);
    const int lane = threadIdx.x & 31;
    const float* xrow = X + (size_t)wid * IN_DIM;
    const float4* w4 = (const float4*)Wg;

    float acc[NM];
#pragma unroll
    for (int n = 0; n < NM; n++) acc[n] = 0.f;

#pragma unroll
    for (int half = 0; half < 2; half++) {
        const int blk = lane + half * 32;
        float f[16];
        const float4* s4 = (const float4*)(xrow + blk * 16);
#pragma unroll
        for (int c = 0; c < 4; c++) {
            float4 v = s4[c];
            f[4 * c] = v.x; f[4 * c + 1] = v.y; f[4 * c + 2] = v.z; f[4 * c + 3] = v.w;
        }
#pragma unroll
        for (int n = 0; n < NM; n++) {
            float a = 0.f;
#pragma unroll
            for (int c = 0; c < 4; c++) {
                const float4 wv = w4[n * 256 + blk * 4 + c];
                a += f[4 * c] * wv.x + f[4 * c + 1] * wv.y
                   + f[4 * c + 2] * wv.z + f[4 * c + 3] * wv.w;
            }
            acc[n] += a;
        }
        uint32_t hs[8], ls[8];
#pragma unroll
        for (int s = 0; s < 8; s++) {
            const float e = f[c_pr[s][0]], o = f[c_pr[s][1]];
            hs[s] = bf2pack(e, o);
            ls[s] = bf2pack(bfres(e), bfres(o));
        }
        const size_t base = (size_t)wid * R512 + blk * 8;
        *(uint4*)(g_Xh + base)     = make_uint4(hs[0], hs[1], hs[2], hs[3]);
        *(uint4*)(g_Xh + base + 4) = make_uint4(hs[4], hs[5], hs[6], hs[7]);
        *(uint4*)(g_Xl + base)     = make_uint4(ls[0], ls[1], ls[2], ls[3]);
        *(uint4*)(g_Xl + base + 4) = make_uint4(ls[4], ls[5], ls[6], ls[7]);
    }

#pragma unroll
    for (int n = 0; n < NM; n++)
#pragma unroll
        for (int off = 16; off > 0; off >>= 1)
            acc[n] += __shfl_xor_sync(0xffffffffu, acc[n], off);

    if (lane == 0) {
        float l[NM], mx = -1e30f;
#pragma unroll
        for (int n = 0; n < NM; n++) { l[n] = acc[n] + Wgb[n]; mx = fmaxf(mx, l[n]); }
        float sc[NM], sum = 0.f;
#pragma unroll
        for (int n = 0; n < NM; n++) { sc[n] = expf(l[n] - mx); sum += sc[n]; }
        const float inv = 1.f / sum;
#pragma unroll
        for (int n = 0; n < NM; n++) sc[n] *= inv;

        int i0 = 0;
#pragma unroll
        for (int n = 1; n < NM; n++) if (sc[n] > sc[i0]) i0 = n;
        int i1 = (i0 == 0) ? 1 : 0;
#pragma unroll
        for (int n = 0; n < NM; n++) if (n != i0 && sc[n] > sc[i1]) i1 = n;

        const float g0 = sc[i0], g1 = sc[i1];
        const float gs = g0 + g1;
        g_ri[wid] = make_int2(i0, i1);
        g_meta[wid] = make_int4(i0, i1, __float_as_int(g0 / gs), __float_as_int(g1 / gs));
    }
}

// ---------------- routing lists ----------------
__global__ __launch_bounds__(256) void listbuild()
{
    const int row = blockIdx.x * 256 + threadIdx.x;
    const int tid = threadIdx.x;
    __shared__ int scnt[8], sbase[8];
    if (tid < 8) scnt[tid] = 0;
    __syncthreads();
    const int2 ii = g_ri[row];
    int p0 = -1, p1 = -1;
    if (ii.x > 0) p0 = atomicAdd(&scnt[ii.x], 1);
    if (ii.y > 0) p1 = atomicAdd(&scnt[ii.y], 1);
    __syncthreads();
    if (tid < 8 && scnt[tid] > 0) sbase[tid] = atomicAdd(&g_cnt[tid], scnt[tid]);
    __syncthreads();
    if (p0 >= 0) g_list[ii.x][sbase[ii.x] + p0] = row;
    if (p1 >= 0) g_list[ii.y][sbase[ii.y] + p1] = row;
}

// ---------------- gathered bf16-split GEMM (m16n8k16, 3 mma per K=16) ----------------
// stage row: 36 u32 = [hi kb0(8) hi kb1(8) | lo kb0(8) lo kb1(8) | pad 4]; 256 rows.
#define STGU 9216              /* u32 per stage */
#define GSMEM (3*STGU*4)       /* 110592 bytes */

__global__ __launch_bounds__(256, 2) void gemm_mma(
    const float* __restrict__ Wk_b, const float* __restrict__ Wv_b,
    const float* __restrict__ Wq_b)
{
    extern __shared__ uint32_t smu[];
    const int tid  = threadIdx.x;
    const int lane = tid & 31;
    const int warp = tid >> 5;
    const int wm = (warp >> 2) * 64;          // 0 or 64
    const int wn = (warp & 3) * 32;           // 0,32,64,96
    const int job = blockIdx.y;               // 0..8
    const int m0 = blockIdx.x * 128;
    const bool isq = (job == 8);
    const int cnt = (job == 0 || isq) ? ROWS : g_cnt[job];
    if (m0 >= cnt) return;

    __shared__ int slist[128];
    if (tid < 128) {
        int idx = m0 + tid;
        int cl = idx < cnt ? idx : cnt - 1;
        slist[tid] = (job == 0 || isq) ? idx : g_list[job][cl];
    }
    __syncthreads();

    // per-thread cp.async descriptors: u 0..3 -> A chunks, 4..7 -> B chunks
    const uint32_t* asrc[4];
    const uint32_t* bsrc[4];
    uint32_t asmo[4], bsmo[4];
    const uint32_t sbase = smem_u32(smu);
#pragma unroll
    for (int u = 0; u < 4; u++) {
        const int id = u * 256 + tid;
        const int row = id >> 3, c8 = id & 7;
        const int c = c8 & 3;
        const bool lo = c8 >= 4;
        asrc[u] = (lo ? g_Xl : g_Xh) + (size_t)slist[row] * R512 + c * 4;
        asmo[u] = (uint32_t)(row * 36 + (lo ? 16 : 0) + c * 4) * 4;
    }
#pragma unroll
    for (int u = 0; u < 4; u++) {
        const int id = (u + 4) * 256 + tid;
        const int row = (id >> 3) - 128, c8 = id & 7;
        const int c = c8 & 3;
        const bool lo = c8 >= 4;
        int br;
        if (!isq) br = (row < 64) ? job * 64 + row : 512 + job * 64 + (row - 64);
        else      br = 1024 + (row & 63);
        bsrc[u] = (lo ? g_Wl : g_Wh) + (size_t)br * R512 + c * 4;
        bsmo[u] = (uint32_t)((128 + row) * 36 + (lo ? 16 : 0) + c * 4) * 4;
    }

    auto loadst = [&](int j) {
        const uint32_t st = sbase + (uint32_t)(j % 3) * (STGU * 4);
        const uint32_t k0 = (uint32_t)j * 16;     // u32 offset within row
#pragma unroll
        for (int u = 0; u < 4; u++) cp16(st + asmo[u], asrc[u] + k0);
#pragma unroll
        for (int u = 0; u < 4; u++) cp16(st + bsmo[u], bsrc[u] + k0);
    };

    loadst(0); cp_commit();
    loadst(1); cp_commit();

    float acc[4][4][4];
#pragma unroll
    for (int mt = 0; mt < 4; mt++)
#pragma unroll
        for (int nt = 0; nt < 4; nt++)
#pragma unroll
            for (int i = 0; i < 4; i++) acc[mt][nt][i] = 0.f;

    const int c4 = lane & 3;
    const int r0 = lane >> 2;

    for (int i = 0; i < 32; i++) {
        cp_wait<1>();
        __syncthreads();
        if (i + 2 < 32) loadst(i + 2);
        cp_commit();

        const uint2* S  = (const uint2*)(smu + (i % 3) * STGU);
        const uint2* As = S;
        const uint2* Bs = S + 128 * 18;
#pragma unroll
        for (int kb = 0; kb < 2; kb++) {
            uint32_t bh[4][2], bl[4][2];
#pragma unroll
            for (int nt = 0; nt < 4; nt++) {
                const int n = wn + nt * 8 + r0;
                const uint2 h = Bs[n * 18 + kb * 4 + c4];
                const uint2 l = Bs[n * 18 + 8 + kb * 4 + c4];
                bh[nt][0] = h.x; bh[nt][1] = h.y;
                bl[nt][0] = l.x; bl[nt][1] = l.y;
            }
#pragma unroll
            for (int mt = 0; mt < 4; mt++) {
                const int r = wm + mt * 16 + r0;
                const uint2 h0 = As[r * 18 + kb * 4 + c4];
                const uint2 h1 = As[(r + 8) * 18 + kb * 4 + c4];
                const uint2 l0 = As[r * 18 + 8 + kb * 4 + c4];
                const uint2 l1 = As[(r + 8) * 18 + 8 + kb * 4 + c4];
                uint32_t ah[4] = { h0.x, h1.x, h0.y, h1.y };
                uint32_t al[4] = { l0.x, l1.x, l0.y, l1.y };
#pragma unroll
                for (int nt = 0; nt < 4; nt++) {
                    mma_bf16(acc[mt][nt], ah, bh[nt]);
                    mma_bf16(acc[mt][nt], ah, bl[nt]);
                    mma_bf16(acc[mt][nt], al, bh[nt]);
                }
            }
        }
    }

    // epilogue (D fragment layout identical to tf32 path)
    if (isq && wn >= 64) return;
#pragma unroll
    for (int mt = 0; mt < 4; mt++) {
#pragma unroll
        for (int half = 0; half < 2; half++) {
            const int lr = wm + mt * 16 + r0 + half * 8;
            if (m0 + lr >= cnt) continue;
            const int row = slist[lr];
#pragma unroll
            for (int nt = 0; nt < 4; nt++) {
                const int col = wn + nt * 8 + c4 * 2;
                const float a0 = acc[mt][nt][half * 2 + 0];
                const float a1 = acc[mt][nt][half * 2 + 1];
                if (isq) {
                    float2 v = { a0 + Wq_b[col], a1 + Wq_b[col + 1] };
                    *(float2*)(g_Cq + (size_t)row * HID + col) = v;
                } else if (col < 64) {
                    float2 v = { a0 + Wk_b[job * 64 + col], a1 + Wk_b[job * 64 + col + 1] };
                    *(float2*)(g_Ck + (size_t)row * NKV + job * 64 + col) = v;
                } else {
                    const int c = col - 64;
                    float2 v = { a0 + Wv_b[job * 64 + c], a1 + Wv_b[job * 64 + c + 1] };
                    *(float2*)(g_Cv + (size_t)row * NKV + job * 64 + c) = v;
                }
            }
        }
    }
}

// ---------------- recurrence: 6-stage cp.async ring, 1 barrier/step ----------------
#define RSTG 208   /* floats per stage: k64 | v64 | q64 | meta4 | pad */

__global__ __launch_bounds__(256) void recur_kernel(
    const float* __restrict__ M0, float* __restrict__ out_m, int write_m)
{
    const int b = blockIdx.x / NM1;
    const int s = blockIdx.x % NM1;
    const int tid = threadIdx.x;
    const int j  = tid >> 2;
    const int ib = tid & 3;

    float Mreg[16];
    const float* m0p = M0 + ((size_t)(b * NM1 + s)) * HID * HID;
#pragma unroll
    for (int r = 0; r < 16; r++) Mreg[r] = m0p[(ib + 4 * r) * HID + j];

    __shared__ float srf[6 * RSTG];
    const uint32_t sring = smem_u32(srf);

    auto load_stage = [&](int t) {
        const uint32_t st = sring + (uint32_t)(t % 6) * (RSTG * 4);
        const int m = t * BATCH + b;
        if (tid < 16)       cp16(st + tid * 16,              g_Ck + (size_t)m * NKV + s * HID + tid * 4);
        else if (tid < 32)  cp16(st + 256 + (tid - 16) * 16, g_Cv + (size_t)m * NKV + s * HID + (tid - 16) * 4);
        else if (tid < 48)  cp16(st + 512 + (tid - 32) * 16, g_Cq + (size_t)m * HID + (tid - 32) * 4);
        else if (tid == 48) cp16(st + 768,                   &g_meta[m]);
    };

#pragma unroll
    for (int t = 0; t < 5; t++) { load_stage(t); cp_commit(); }

    for (int t = 0; t < SEQ; t++) {
        cp_wait<4>();
        __syncthreads();
        if (t + 5 < SEQ) load_stage(t + 5);
        cp_commit();

        const float* st = srf + (t % 6) * RSTG;
        const int* sti = (const int*)st;
        const int i0 = sti[192], i1 = sti[193];
        const float gg0 = st[194], gg1 = st[195];

        float cf = 0.f, w = 0.f;
        if (s == 0)  { cf += 1.f; w += 1.f; }
        if (s == i0) { cf += 1.f; w += gg0; }
        if (s == i1) { cf += 1.f; w += gg1; }

        const float vj = st[64 + j];
        if (cf != 0.f) {
            const float cv = cf * vj;
#pragma unroll
            for (int r = 0; r < 16; r++)
                Mreg[r] = fmaf(st[ib + 4 * r], cv, Mreg[r]);
        }

        float p0 = 0.f, p1 = 0.f;
#pragma unroll
        for (int r = 0; r < 8; r++) {
            p0 = fmaf(st[128 + ib + 8 * r],     Mreg[2 * r],     p0);
            p1 = fmaf(st[128 + ib + 8 * r + 4], Mreg[2 * r + 1], p1);
        }
        float p = p0 + p1;
        p += __shfl_xor_sync(0xffffffffu, p, 1);
        p += __shfl_xor_sync(0xffffffffu, p, 2);

        if (ib == 0) {
            const int row = t * BATCH + b;
            const int pos = (s == 0) ? 0 : (s == i0) ? 1 : (s == i1) ? 2 : -1;
            if (pos >= 0) g_c3[((size_t)row * 3 + pos) * HID + j] = w * p;
            if (s == 0) {
                if (i0 == 0) g_c3[((size_t)row * 3 + 1) * HID + j] = 0.f;
                if (i1 == 0) g_c3[((size_t)row * 3 + 2) * HID + j] = 0.f;
            }
        }
    }

    if (write_m) {
        float* mo = out_m + ((size_t)(b * NM1 + s)) * HID * HID;
#pragma unroll
        for (int r = 0; r < 16; r++) mo[(ib + 4 * r) * HID + j] = Mreg[r];
    }
}

// ---------------- finalize ----------------
__global__ __launch_bounds__(256) void finalize_kernel(float* __restrict__ out)
{
    const int idx = blockIdx.x * 256 + threadIdx.x;
    const int tb = idx >> 6, j = idx & 63;
    out[idx] = g_c3[((size_t)tb * 3 + 0) * HID + j]
             + g_c3[((size_t)tb * 3 + 1) * HID + j]
             + g_c3[((size_t)tb * 3 + 2) * HID + j];
}

// ---------------- launch ----------------
extern "C" void kernel_launch(void* const* d_in, const int* in_sizes, int n_in,
                              void* d_out, int out_size)
{
    const float* X    = (const float*)d_in[0];
    const float* M0   = (const float*)d_in[1];
    const float* Wk_w = (const float*)d_in[2];
    const float* Wk_b = (const float*)d_in[3];
    const float* Wv_w = (const float*)d_in[4];
    const float* Wv_b = (const float*)d_in[5];
    const float* Wg_w = (const float*)d_in[6];
    const float* Wg_b = (const float*)d_in[7];
    const float* Wq_w = (const float*)d_in[8];
    const float* Wq_b = (const float*)d_in[9];
    float* out = (float*)d_out;

    prep_w<<<(WROWS * 64 + 255) / 256, 256>>>(Wk_w, Wv_w, Wq_w);   // also zeroes g_cnt
    gate_kernel<<<ROWS / 8, 256>>>(X, Wg_w, Wg_b);                 // writes split X + meta
    listbuild<<<ROWS / 256, 256>>>();

    cudaFuncSetAttribute(gemm_mma, cudaFuncAttributeMaxDynamicSharedMemorySize, GSMEM);
    gemm_mma<<<dim3(64, 9), 256, GSMEM>>>(Wk_b, Wv_b, Wq_b);

    const long OUTSEQ = (long)SEQ * BATCH * HID;            // 524288
    const long MTOT   = (long)BATCH * NM1 * HID * HID;      // 1179648
    const int write_m = ((long)out_size >= OUTSEQ + MTOT) ? 1 : 0;

    recur_kernel<<<BATCH * NM1, 256>>>(M0, out + OUTSEQ, write_m);
    finalize_kernel<<<(int)(OUTSEQ / 256), 256>>>(out);
}

// round 7
// speedup vs baseline: 1.0474x; 1.0474x over previous
#include <cuda_runtime.h>
#include <cstdint>
#include <cstddef>

#define SEQ 256
#define BATCH 32
#define IN_DIM 1024
#define HID 64
#define NM 8
#define NM1 9
#define ROWS (SEQ*BATCH)     /* 8192 */
#define NKV (NM1*HID)        /* 576  */

// ---------------- scratch (device globals; no allocation allowed) ----------------
__device__ float  g_Xr[(size_t)ROWS * IN_DIM];     // tf32-rounded, k-pair-permuted X
__device__ float  g_Wr[(size_t)1216 * IN_DIM];     // tf32-rounded, permuted Wk|Wv|Wq
__device__ float  g_Ck[(size_t)ROWS * NKV];
__device__ float  g_Cv[(size_t)ROWS * NKV];
__device__ float  g_Cq[(size_t)ROWS * HID];
__device__ int2   g_ri[ROWS];
__device__ int4   g_meta[ROWS];                    // {i0, i1, bits(g0), bits(g1)}
__device__ int    g_list[8][ROWS];
__device__ int    g_cnt[8];
__device__ float  g_c3[(size_t)ROWS * 3 * HID];    // compact contribs

// ---------------- helpers ----------------
__device__ __forceinline__ uint32_t smem_u32(const void* p) {
    uint32_t a;
    asm("{ .reg .u64 t; cvta.to.shared.u64 t, %1; cvt.u32.u64 %0, t; }" : "=r"(a) : "l"(p));
    return a;
}
__device__ __forceinline__ void cp16(uint32_t dst, const void* src) {
    asm volatile("cp.async.cg.shared.global [%0], [%1], 16;\n" :: "r"(dst), "l"(src) : "memory");
}
__device__ __forceinline__ void cp_commit() { asm volatile("cp.async.commit_group;\n" ::: "memory"); }
template<int N> __device__ __forceinline__ void cp_wait() {
    asm volatile("cp.async.wait_group %0;\n" :: "n"(N) : "memory");
}
__device__ __forceinline__ float f2tf_rna(float f) {
    uint32_t u;
    asm("cvt.rna.tf32.f32 %0, %1;" : "=r"(u) : "f"(f));
    return __uint_as_float(u);
}
__device__ __forceinline__ void mma_tf32(float* d, const uint32_t* a, const uint32_t* b) {
    asm volatile(
        "mma.sync.aligned.m16n8k8.row.col.f32.tf32.tf32.f32 "
        "{%0,%1,%2,%3},{%4,%5,%6,%7},{%8,%9},{%0,%1,%2,%3};"
        : "+f"(d[0]), "+f"(d[1]), "+f"(d[2]), "+f"(d[3])
        : "r"(a[0]), "r"(a[1]), "r"(a[2]), "r"(a[3]), "r"(b[0]), "r"(b[1]));
}

// ---------------- weights: tf32 round + k-pair permute ----------------
// within each 8-float k-block: dst position p holds src sigma(p), sigma=[0,4,1,5,2,6,3,7]
__global__ __launch_bounds__(256) void round_perm(const float* __restrict__ src,
                                                  float* __restrict__ dst, int nblk)
{
    int i = blockIdx.x * 256 + threadIdx.x;
    if (i >= nblk) return;
    const float4* s4 = (const float4*)src;
    float4* d4 = (float4*)dst;
    float4 a = s4[2 * i], b = s4[2 * i + 1];
    float4 o0 = { f2tf_rna(a.x), f2tf_rna(b.x), f2tf_rna(a.y), f2tf_rna(b.y) };
    float4 o1 = { f2tf_rna(a.z), f2tf_rna(b.z), f2tf_rna(a.w), f2tf_rna(b.w) };
    d4[2 * i] = o0;
    d4[2 * i + 1] = o1;
}

// ---------------- gate: exact fp32 logits + softmax + top-2; writes permuted Xr ----------------
__global__ __launch_bounds__(256) void gate_kernel(
    const float* __restrict__ X, const float* __restrict__ Wg,
    const float* __restrict__ Wgb)
{
    const int wid  = blockIdx.x * 8 + (threadIdx.x >> 5);
    const int lane = threadIdx.x & 31;
    const float4* x4 = (const float4*)(X + (size_t)wid * IN_DIM);
    float4* xo = (float4*)(g_Xr + (size_t)wid * IN_DIM);
    const float4* w4 = (const float4*)Wg;

    float acc[NM];
#pragma unroll
    for (int n = 0; n < NM; n++) acc[n] = 0.f;

#pragma unroll
    for (int c = 0; c < 4; c++) {
        const int blk = c * 32 + lane;          // 8-float block index (0..127)
        const float4 a = x4[2 * blk];
        const float4 b = x4[2 * blk + 1];
#pragma unroll
        for (int n = 0; n < NM; n++) {
            const float4 wa = w4[n * 256 + 2 * blk];
            const float4 wb = w4[n * 256 + 2 * blk + 1];
            acc[n] += a.x * wa.x + a.y * wa.y + a.z * wa.z + a.w * wa.w
                    + b.x * wb.x + b.y * wb.y + b.z * wb.z + b.w * wb.w;
        }
        float4 o0 = { f2tf_rna(a.x), f2tf_rna(b.x), f2tf_rna(a.y), f2tf_rna(b.y) };
        float4 o1 = { f2tf_rna(a.z), f2tf_rna(b.z), f2tf_rna(a.w), f2tf_rna(b.w) };
        xo[2 * blk] = o0;
        xo[2 * blk + 1] = o1;
    }

#pragma unroll
    for (int n = 0; n < NM; n++)
#pragma unroll
        for (int off = 16; off > 0; off >>= 1)
            acc[n] += __shfl_xor_sync(0xffffffffu, acc[n], off);

    if (lane == 0) {
        float l[NM], mx = -1e30f;
#pragma unroll
        for (int n = 0; n < NM; n++) { l[n] = acc[n] + Wgb[n]; mx = fmaxf(mx, l[n]); }
        float sc[NM], sum = 0.f;
#pragma unroll
        for (int n = 0; n < NM; n++) { sc[n] = expf(l[n] - mx); sum += sc[n]; }
        const float inv = 1.f / sum;
#pragma unroll
        for (int n = 0; n < NM; n++) sc[n] *= inv;

        int i0 = 0;
#pragma unroll
        for (int n = 1; n < NM; n++) if (sc[n] > sc[i0]) i0 = n;
        int i1 = (i0 == 0) ? 1 : 0;
#pragma unroll
        for (int n = 0; n < NM; n++) if (n != i0 && sc[n] > sc[i1]) i1 = n;

        const float g0 = sc[i0], g1 = sc[i1];
        const float gs = g0 + g1;
        g_ri[wid] = make_int2(i0, i1);
        g_meta[wid] = make_int4(i0, i1, __float_as_int(g0 / gs), __float_as_int(g1 / gs));
    }
}

// ---------------- routing lists ----------------
__global__ void zero_cnt() { if (threadIdx.x < 8) g_cnt[threadIdx.x] = 0; }

__global__ __launch_bounds__(256) void listbuild()
{
    const int row = blockIdx.x * 256 + threadIdx.x;
    const int tid = threadIdx.x;
    __shared__ int scnt[8], sbase[8];
    if (tid < 8) scnt[tid] = 0;
    __syncthreads();
    const int2 ii = g_ri[row];
    int p0 = -1, p1 = -1;
    if (ii.x > 0) p0 = atomicAdd(&scnt[ii.x], 1);
    if (ii.y > 0) p1 = atomicAdd(&scnt[ii.y], 1);
    __syncthreads();
    if (tid < 8 && scnt[tid] > 0) sbase[tid] = atomicAdd(&g_cnt[tid], scnt[tid]);
    __syncthreads();
    if (p0 >= 0) g_list[ii.x][sbase[ii.x] + p0] = row;
    if (p1 >= 0) g_list[ii.y][sbase[ii.y] + p1] = row;
}

// ---------------- gathered tf32 mma.sync GEMM (LDS.64 fragments) ----------------
// ISQ=0: jobs 0..7 (grid.y), N=128 (k|v), warp tile 64x32.
// ISQ=1: q job, N=64, warp tile 64x16 (half the mma work).
#define STGF 9216              /* (128+128)*36 floats per stage */
#define GSMEM (3*STGF*4)       /* 110592 bytes */

template<int ISQ>
__global__ __launch_bounds__(256, 2) void gemm_mma(
    const float* __restrict__ Wk_b, const float* __restrict__ Wv_b,
    const float* __restrict__ Wq_b)
{
    extern __shared__ float smf[];
    const int tid  = threadIdx.x;
    const int lane = tid & 31;
    const int warp = tid >> 5;
    const int wm = (warp >> 2) * 64;                       // 0 or 64
    const int wn = ISQ ? (warp & 3) * 16 : (warp & 3) * 32;
    const int NT = ISQ ? 2 : 4;
    const int job = ISQ ? 8 : blockIdx.y;                  // 0..7 or q
    const int m0 = blockIdx.x * 128;
    const int cnt = (ISQ || job == 0) ? ROWS : g_cnt[job];
    if (m0 >= cnt) return;

    __shared__ int slist[128];
    if (tid < 128) {
        int idx = m0 + tid;
        int cl = idx < cnt ? idx : cnt - 1;
        slist[tid] = (ISQ || job == 0) ? idx : g_list[job][cl];
    }
    __syncthreads();

    uint32_t aoff[4], asmo[4], boff[4], bsmo[4];
    const uint32_t sbase = smem_u32(smf);
#pragma unroll
    for (int u = 0; u < 4; u++) {
        const int id = u * 256 + tid;
        const int row = id >> 3, c16 = id & 7;
        aoff[u] = (uint32_t)slist[row] * IN_DIM + c16 * 4;
        asmo[u] = (uint32_t)(row * 36 + c16 * 4) * 4;
        int br;
        if (!ISQ) br = (row < 64) ? job * 64 + row : 576 + job * 64 + (row - 64);
        else      br = 1152 + (row & 63);
        boff[u] = (uint32_t)br * IN_DIM + c16 * 4;
        bsmo[u] = (uint32_t)(128 * 36 + row * 36 + c16 * 4) * 4;
    }

    auto loadst = [&](int j) {
        const uint32_t st = sbase + (uint32_t)(j % 3) * (STGF * 4);
        const uint32_t k0 = (uint32_t)j * 32;
#pragma unroll
        for (int u = 0; u < 4; u++) cp16(st + asmo[u], g_Xr + aoff[u] + k0);
#pragma unroll
        for (int u = 0; u < 4; u++) cp16(st + bsmo[u], g_Wr + boff[u] + k0);
    };

    loadst(0); cp_commit();
    loadst(1); cp_commit();

    float acc[4][4][4];
#pragma unroll
    for (int mt = 0; mt < 4; mt++)
#pragma unroll
        for (int nt = 0; nt < NT; nt++)
#pragma unroll
            for (int i = 0; i < 4; i++) acc[mt][nt][i] = 0.f;

    const int c4 = lane & 3;
    const int r0 = lane >> 2;

    for (int i = 0; i < 32; i++) {
        cp_wait<1>();
        __syncthreads();
        if (i + 2 < 32) loadst(i + 2);
        cp_commit();

        const float2* As2 = (const float2*)(smf + (i % 3) * STGF);
        const float2* Bs2 = As2 + 128 * 18;
#pragma unroll
        for (int ks = 0; ks < 4; ks++) {
            uint32_t af[4][4], bf[4][2];
#pragma unroll
            for (int mt = 0; mt < 4; mt++) {
                const int ra = (wm + mt * 16 + r0) * 18 + ks * 4 + c4;
                const float2 pr  = As2[ra];
                const float2 pr8 = As2[ra + 8 * 18];
                af[mt][0] = __float_as_uint(pr.x);
                af[mt][1] = __float_as_uint(pr8.x);
                af[mt][2] = __float_as_uint(pr.y);
                af[mt][3] = __float_as_uint(pr8.y);
            }
#pragma unroll
            for (int nt = 0; nt < NT; nt++) {
                const int nb = (wn + nt * 8 + r0) * 18 + ks * 4 + c4;
                const float2 bv = Bs2[nb];
                bf[nt][0] = __float_as_uint(bv.x);
                bf[nt][1] = __float_as_uint(bv.y);
            }
#pragma unroll
            for (int mt = 0; mt < 4; mt++)
#pragma unroll
                for (int nt = 0; nt < NT; nt++)
                    mma_tf32(acc[mt][nt], af[mt], bf[nt]);
        }
    }

    // epilogue
#pragma unroll
    for (int mt = 0; mt < 4; mt++) {
#pragma unroll
        for (int half = 0; half < 2; half++) {
            const int lr = wm + mt * 16 + r0 + half * 8;
            if (m0 + lr >= cnt) continue;
            const int row = slist[lr];
#pragma unroll
            for (int nt = 0; nt < NT; nt++) {
                const int col = wn + nt * 8 + c4 * 2;
                const float a0 = acc[mt][nt][half * 2 + 0];
                const float a1 = acc[mt][nt][half * 2 + 1];
                if (ISQ) {
                    float2 v = { a0 + Wq_b[col], a1 + Wq_b[col + 1] };
                    *(float2*)(g_Cq + (size_t)row * HID + col) = v;
                } else if (col < 64) {
                    float2 v = { a0 + Wk_b[job * 64 + col], a1 + Wk_b[job * 64 + col + 1] };
                    *(float2*)(g_Ck + (size_t)row * NKV + job * 64 + col) = v;
                } else {
                    const int c = col - 64;
                    float2 v = { a0 + Wv_b[job * 64 + c], a1 + Wv_b[job * 64 + c + 1] };
                    *(float2*)(g_Cv + (size_t)row * NKV + job * 64 + c) = v;
                }
            }
        }
    }
}

// ---------------- recurrence: 8-stage cp.async ring, 1 barrier per 2 steps ----------------
// thread mapping: j = tid>>2 (column), ib = tid&3; Mreg[r] = M[ib+4r][j]
#define RSTG 208   /* floats per stage: k64 | v64 | q64 | meta4 | pad */

__global__ __launch_bounds__(256) void recur_kernel(
    const float* __restrict__ M0, float* __restrict__ out_m, int write_m)
{
    const int b = blockIdx.x / NM1;
    const int s = blockIdx.x % NM1;
    const int tid = threadIdx.x;
    const int j  = tid >> 2;
    const int ib = tid & 3;

    float Mreg[16];
    const float* m0p = M0 + ((size_t)(b * NM1 + s)) * HID * HID;
#pragma unroll
    for (int r = 0; r < 16; r++) Mreg[r] = m0p[(ib + 4 * r) * HID + j];

    __shared__ float srf[8 * RSTG];
    const uint32_t sring = smem_u32(srf);

    auto load_stage = [&](int t) {
        const uint32_t st = sring + (uint32_t)(t & 7) * (RSTG * 4);
        const int m = t * BATCH + b;
        if (tid < 16)       cp16(st + tid * 16,              g_Ck + (size_t)m * NKV + s * HID + tid * 4);
        else if (tid < 32)  cp16(st + 256 + (tid - 16) * 16, g_Cv + (size_t)m * NKV + s * HID + (tid - 16) * 4);
        else if (tid < 48)  cp16(st + 512 + (tid - 32) * 16, g_Cq + (size_t)m * HID + (tid - 32) * 4);
        else if (tid == 48) cp16(st + 768,                   &g_meta[m]);
    };

    auto do_step = [&](int t) {
        const float* st = srf + (t & 7) * RSTG;
        const int* sti = (const int*)st;
        const int i0 = sti[192], i1 = sti[193];
        const float gg0 = st[194], gg1 = st[195];

        float cf = 0.f, w = 0.f;
        if (s == 0)  { cf += 1.f; w += 1.f; }
        if (s == i0) { cf += 1.f; w += gg0; }
        if (s == i1) { cf += 1.f; w += gg1; }

        const float vj = st[64 + j];
        if (cf != 0.f) {
            const float cv = cf * vj;
#pragma unroll
            for (int r = 0; r < 16; r++)
                Mreg[r] = fmaf(st[ib + 4 * r], cv, Mreg[r]);
        }

        float p0 = 0.f, p1 = 0.f;
#pragma unroll
        for (int r = 0; r < 8; r++) {
            p0 = fmaf(st[128 + ib + 8 * r],     Mreg[2 * r],     p0);
            p1 = fmaf(st[128 + ib + 8 * r + 4], Mreg[2 * r + 1], p1);
        }
        float p = p0 + p1;
        p += __shfl_xor_sync(0xffffffffu, p, 1);
        p += __shfl_xor_sync(0xffffffffu, p, 2);

        if (ib == 0) {
            const int row = t * BATCH + b;
            const int pos = (s == 0) ? 0 : (s == i0) ? 1 : (s == i1) ? 2 : -1;
            if (pos >= 0) g_c3[((size_t)row * 3 + pos) * HID + j] = w * p;
            if (s == 0) {
                if (i0 == 0) g_c3[((size_t)row * 3 + 1) * HID + j] = 0.f;
                if (i1 == 0) g_c3[((size_t)row * 3 + 2) * HID + j] = 0.f;
            }
        }
    };

    // preload stages 0..5 (6 commit groups)
#pragma unroll
    for (int t = 0; t < 6; t++) { load_stage(t); cp_commit(); }

    for (int i = 0; i < SEQ / 2; i++) {
        const int t0 = 2 * i;
        cp_wait<4>();            // completes the 2 oldest groups -> stages t0, t0+1 ready
        __syncthreads();
        if (t0 + 6 < SEQ) load_stage(t0 + 6);
        cp_commit();
        if (t0 + 7 < SEQ) load_stage(t0 + 7);
        cp_commit();
        do_step(t0);
        do_step(t0 + 1);
    }

    if (write_m) {
        float* mo = out_m + ((size_t)(b * NM1 + s)) * HID * HID;
#pragma unroll
        for (int r = 0; r < 16; r++) mo[(ib + 4 * r) * HID + j] = Mreg[r];
    }
}

// ---------------- finalize: o[t,b,j] = sum of 3 compact contribs ----------------
__global__ __launch_bounds__(256) void finalize_kernel(float* __restrict__ out)
{
    const int idx = blockIdx.x * 256 + threadIdx.x;
    const int tb = idx >> 6, j = idx & 63;
    out[idx] = g_c3[((size_t)tb * 3 + 0) * HID + j]
             + g_c3[((size_t)tb * 3 + 1) * HID + j]
             + g_c3[((size_t)tb * 3 + 2) * HID + j];
}

// ---------------- launch ----------------
extern "C" void kernel_launch(void* const* d_in, const int* in_sizes, int n_in,
                              void* d_out, int out_size)
{
    const float* X    = (const float*)d_in[0];
    const float* M0   = (const float*)d_in[1];
    const float* Wk_w = (const float*)d_in[2];
    const float* Wk_b = (const float*)d_in[3];
    const float* Wv_w = (const float*)d_in[4];
    const float* Wv_b = (const float*)d_in[5];
    const float* Wg_w = (const float*)d_in[6];
    const float* Wg_b = (const float*)d_in[7];
    const float* Wq_w = (const float*)d_in[8];
    const float* Wq_b = (const float*)d_in[9];
    float* out = (float*)d_out;

    float* pWr;
    cudaGetSymbolAddress((void**)&pWr, g_Wr);

    // round+permute stacked weights
    {
        const int nkb = NKV * IN_DIM / 8;                   // 73728 blocks
        round_perm<<<(nkb + 255) / 256, 256>>>(Wk_w, pWr, nkb);
        round_perm<<<(nkb + 255) / 256, 256>>>(Wv_w, pWr + (size_t)576 * IN_DIM, nkb);
        const int nqb = HID * IN_DIM / 8;                   // 8192 blocks
        round_perm<<<(nqb + 255) / 256, 256>>>(Wq_w, pWr + (size_t)1152 * IN_DIM, nqb);
    }

    gate_kernel<<<ROWS / 8, 256>>>(X, Wg_w, Wg_b);          // also writes permuted g_Xr + meta
    zero_cnt<<<1, 32>>>();
    listbuild<<<ROWS / 256, 256>>>();

    cudaFuncSetAttribute(gemm_mma<0>, cudaFuncAttributeMaxDynamicSharedMemorySize, GSMEM);
    cudaFuncSetAttribute(gemm_mma<1>, cudaFuncAttributeMaxDynamicSharedMemorySize, GSMEM);
    gemm_mma<0><<<dim3(64, 8), 256, GSMEM>>>(Wk_b, Wv_b, Wq_b);
    gemm_mma<1><<<dim3(64, 1), 256, GSMEM>>>(Wk_b, Wv_b, Wq_b);

    const long OUTSEQ = (long)SEQ * BATCH * HID;            // 524288
    const long MTOT   = (long)BATCH * NM1 * HID * HID;      // 1179648
    const int write_m = ((long)out_size >= OUTSEQ + MTOT) ? 1 : 0;

    recur_kernel<<<BATCH * NM1, 256>>>(M0, out + OUTSEQ, write_m);
    finalize_kernel<<<(int)(OUTSEQ / 256), 256>>>(out);
}

// round 8
// speedup vs baseline: 1.2342x; 1.1784x over previous
#include <cuda_runtime.h>
#include <cstdint>
#include <cstddef>

#define SEQ 256
#define BATCH 32
#define IN_DIM 1024
#define HID 64
#define NM 8
#define NM1 9
#define ROWS (SEQ*BATCH)     /* 8192 */
#define NKV (NM1*HID)        /* 576  */

// ---------------- scratch (device globals; no allocation allowed) ----------------
__device__ float  g_Xr[(size_t)ROWS * IN_DIM];     // tf32-rounded, k-pair-permuted X
__device__ float  g_Wr[(size_t)1216 * IN_DIM];     // tf32-rounded, permuted Wk|Wv|Wq
__device__ float  g_Ck[(size_t)ROWS * NKV];
__device__ float  g_Cv[(size_t)ROWS * NKV];
__device__ float  g_Cq[(size_t)ROWS * HID];
__device__ int2   g_ri[ROWS];
__device__ int4   g_meta[ROWS];                    // {i0, i1, bits(g0), bits(g1)}
__device__ int    g_list[8][ROWS];
__device__ int    g_cnt[8];
__device__ float  g_c3[(size_t)ROWS * 3 * HID];    // compact contribs

// ---------------- helpers ----------------
__device__ __forceinline__ uint32_t smem_u32(const void* p) {
    uint32_t a;
    asm("{ .reg .u64 t; cvta.to.shared.u64 t, %1; cvt.u32.u64 %0, t; }" : "=r"(a) : "l"(p));
    return a;
}
__device__ __forceinline__ void cp16(uint32_t dst, const void* src) {
    asm volatile("cp.async.cg.shared.global [%0], [%1], 16;\n" :: "r"(dst), "l"(src) : "memory");
}
__device__ __forceinline__ void cp_commit() { asm volatile("cp.async.commit_group;\n" ::: "memory"); }
template<int N> __device__ __forceinline__ void cp_wait() {
    asm volatile("cp.async.wait_group %0;\n" :: "n"(N) : "memory");
}
__device__ __forceinline__ float f2tf_rna(float f) {
    uint32_t u;
    asm("cvt.rna.tf32.f32 %0, %1;" : "=r"(u) : "f"(f));
    return __uint_as_float(u);
}
__device__ __forceinline__ void mma_tf32(float* d, const uint32_t* a, const uint32_t* b) {
    asm volatile(
        "mma.sync.aligned.m16n8k8.row.col.f32.tf32.tf32.f32 "
        "{%0,%1,%2,%3},{%4,%5,%6,%7},{%8,%9},{%0,%1,%2,%3};"
        : "+f"(d[0]), "+f"(d[1]), "+f"(d[2]), "+f"(d[3])
        : "r"(a[0]), "r"(a[1]), "r"(a[2]), "r"(a[3]), "r"(b[0]), "r"(b[1]));
}

// ---------------- fused gate + weight prep ----------------
// blocks [0,1024): gating (8 warps = 8 rows each) + permuted tf32 X write.
// blocks [1024,1632): round+permute stacked weights Wk|Wv|Wq into g_Wr.
// permute within each 8-float k-block: dst p holds src sigma(p), sigma=[0,4,1,5,2,6,3,7]
#define GATE_BLKS 1024
#define WPREP_BLKS 608          /* 1216 rows * 128 blocks / 256 threads */

__global__ __launch_bounds__(256) void gate_prep(
    const float* __restrict__ X, const float* __restrict__ Wg,
    const float* __restrict__ Wgb,
    const float* __restrict__ Wk, const float* __restrict__ Wv,
    const float* __restrict__ Wq)
{
    if (blockIdx.x == 0 && threadIdx.x < 8) g_cnt[threadIdx.x] = 0;

    if (blockIdx.x >= GATE_BLKS) {
        // ---- weight prep ----
        const int i = (blockIdx.x - GATE_BLKS) * 256 + threadIdx.x;  // 8-float block id
        const int row = i >> 7;          // 0..1215
        const int blk = i & 127;
        const float* src;
        if (row < 576)       src = Wk + (size_t)row * IN_DIM;
        else if (row < 1152) src = Wv + (size_t)(row - 576) * IN_DIM;
        else                 src = Wq + (size_t)(row - 1152) * IN_DIM;
        const float4* s4 = (const float4*)(src + blk * 8);
        float4 a = s4[0], b = s4[1];
        float4 o0 = { f2tf_rna(a.x), f2tf_rna(b.x), f2tf_rna(a.y), f2tf_rna(b.y) };
        float4 o1 = { f2tf_rna(a.z), f2tf_rna(b.z), f2tf_rna(a.w), f2tf_rna(b.w) };
        float4* d4 = (float4*)(g_Wr + (size_t)row * IN_DIM + blk * 8);
        d4[0] = o0;
        d4[1] = o1;
        return;
    }

    // ---- gating ----
    const int wid  = blockIdx.x * 8 + (threadIdx.x >> 5);
    const int lane = threadIdx.x & 31;
    const float4* x4 = (const float4*)(X + (size_t)wid * IN_DIM);
    float4* xo = (float4*)(g_Xr + (size_t)wid * IN_DIM);
    const float4* w4 = (const float4*)Wg;

    float acc[NM];
#pragma unroll
    for (int n = 0; n < NM; n++) acc[n] = 0.f;

#pragma unroll
    for (int c = 0; c < 4; c++) {
        const int blk = c * 32 + lane;          // 8-float block index (0..127)
        const float4 a = x4[2 * blk];
        const float4 b = x4[2 * blk + 1];
#pragma unroll
        for (int n = 0; n < NM; n++) {
            const float4 wa = w4[n * 256 + 2 * blk];
            const float4 wb = w4[n * 256 + 2 * blk + 1];
            acc[n] += a.x * wa.x + a.y * wa.y + a.z * wa.z + a.w * wa.w
                    + b.x * wb.x + b.y * wb.y + b.z * wb.z + b.w * wb.w;
        }
        float4 o0 = { f2tf_rna(a.x), f2tf_rna(b.x), f2tf_rna(a.y), f2tf_rna(b.y) };
        float4 o1 = { f2tf_rna(a.z), f2tf_rna(b.z), f2tf_rna(a.w), f2tf_rna(b.w) };
        xo[2 * blk] = o0;
        xo[2 * blk + 1] = o1;
    }

#pragma unroll
    for (int n = 0; n < NM; n++)
#pragma unroll
        for (int off = 16; off > 0; off >>= 1)
            acc[n] += __shfl_xor_sync(0xffffffffu, acc[n], off);

    if (lane == 0) {
        float l[NM], mx = -1e30f;
#pragma unroll
        for (int n = 0; n < NM; n++) { l[n] = acc[n] + Wgb[n]; mx = fmaxf(mx, l[n]); }
        float sc[NM], sum = 0.f;
#pragma unroll
        for (int n = 0; n < NM; n++) { sc[n] = expf(l[n] - mx); sum += sc[n]; }
        const float inv = 1.f / sum;
#pragma unroll
        for (int n = 0; n < NM; n++) sc[n] *= inv;

        int i0 = 0;
#pragma unroll
        for (int n = 1; n < NM; n++) if (sc[n] > sc[i0]) i0 = n;
        int i1 = (i0 == 0) ? 1 : 0;
#pragma unroll
        for (int n = 0; n < NM; n++) if (n != i0 && sc[n] > sc[i1]) i1 = n;

        const float g0 = sc[i0], g1 = sc[i1];
        const float gs = g0 + g1;
        g_ri[wid] = make_int2(i0, i1);
        g_meta[wid] = make_int4(i0, i1, __float_as_int(g0 / gs), __float_as_int(g1 / gs));
    }
}

// ---------------- routing lists ----------------
__global__ __launch_bounds__(256) void listbuild()
{
    const int row = blockIdx.x * 256 + threadIdx.x;
    const int tid = threadIdx.x;
    __shared__ int scnt[8], sbase[8];
    if (tid < 8) scnt[tid] = 0;
    __syncthreads();
    const int2 ii = g_ri[row];
    int p0 = -1, p1 = -1;
    if (ii.x > 0) p0 = atomicAdd(&scnt[ii.x], 1);
    if (ii.y > 0) p1 = atomicAdd(&scnt[ii.y], 1);
    __syncthreads();
    if (tid < 8 && scnt[tid] > 0) sbase[tid] = atomicAdd(&g_cnt[tid], scnt[tid]);
    __syncthreads();
    if (p0 >= 0) g_list[ii.x][sbase[ii.x] + p0] = row;
    if (p1 >= 0) g_list[ii.y][sbase[ii.y] + p1] = row;
}

// ---------------- gathered tf32 mma.sync GEMM (LDS.64 fragments) ----------------
// jobs 0..7: slot s; N=128 (k|v). job 8: q; warps with wn>=64 skip mma work.
#define STGF 9216              /* (128+128)*36 floats per stage */
#define GSMEM (3*STGF*4)       /* 110592 bytes */

__global__ __launch_bounds__(256, 2) void gemm_mma(
    const float* __restrict__ Wk_b, const float* __restrict__ Wv_b,
    const float* __restrict__ Wq_b)
{
    extern __shared__ float smf[];
    const int tid  = threadIdx.x;
    const int lane = tid & 31;
    const int warp = tid >> 5;
    const int wm = (warp >> 2) * 64;          // 0 or 64
    const int wn = (warp & 3) * 32;           // 0,32,64,96
    const int job = blockIdx.y;               // 0..8
    const int m0 = blockIdx.x * 128;
    const bool isq = (job == 8);
    const int cnt = (job == 0 || isq) ? ROWS : g_cnt[job];
    if (m0 >= cnt) return;
    const bool active = !(isq && wn >= 64);   // q job: cols>=64 are waste

    __shared__ int slist[128];
    if (tid < 128) {
        int idx = m0 + tid;
        int cl = idx < cnt ? idx : cnt - 1;
        slist[tid] = (job == 0 || isq) ? idx : g_list[job][cl];
    }
    __syncthreads();

    uint32_t aoff[4], asmo[4], boff[4], bsmo[4];
    const uint32_t sbase = smem_u32(smf);
#pragma unroll
    for (int u = 0; u < 4; u++) {
        const int id = u * 256 + tid;
        const int row = id >> 3, c16 = id & 7;
        aoff[u] = (uint32_t)slist[row] * IN_DIM + c16 * 4;
        asmo[u] = (uint32_t)(row * 36 + c16 * 4) * 4;
        int br;
        if (!isq) br = (row < 64) ? job * 64 + row : 576 + job * 64 + (row - 64);
        else      br = 1152 + (row & 63);
        boff[u] = (uint32_t)br * IN_DIM + c16 * 4;
        bsmo[u] = (uint32_t)(128 * 36 + row * 36 + c16 * 4) * 4;
    }

    auto loadst = [&](int j) {
        const uint32_t st = sbase + (uint32_t)(j % 3) * (STGF * 4);
        const uint32_t k0 = (uint32_t)j * 32;
#pragma unroll
        for (int u = 0; u < 4; u++) cp16(st + asmo[u], g_Xr + aoff[u] + k0);
#pragma unroll
        for (int u = 0; u < 4; u++) cp16(st + bsmo[u], g_Wr + boff[u] + k0);
    };

    loadst(0); cp_commit();
    loadst(1); cp_commit();

    float acc[4][4][4];
#pragma unroll
    for (int mt = 0; mt < 4; mt++)
#pragma unroll
        for (int nt = 0; nt < 4; nt++)
#pragma unroll
            for (int i = 0; i < 4; i++) acc[mt][nt][i] = 0.f;

    const int c4 = lane & 3;
    const int r0 = lane >> 2;

    for (int i = 0; i < 32; i++) {
        cp_wait<1>();
        __syncthreads();
        if (i + 2 < 32) loadst(i + 2);
        cp_commit();

        if (active) {
            const float2* As2 = (const float2*)(smf + (i % 3) * STGF);
            const float2* Bs2 = As2 + 128 * 18;
#pragma unroll
            for (int ks = 0; ks < 4; ks++) {
                uint32_t af[4][4], bf[4][2];
#pragma unroll
                for (int mt = 0; mt < 4; mt++) {
                    const int ra = (wm + mt * 16 + r0) * 18 + ks * 4 + c4;
                    const float2 pr  = As2[ra];
                    const float2 pr8 = As2[ra + 8 * 18];
                    af[mt][0] = __float_as_uint(pr.x);
                    af[mt][1] = __float_as_uint(pr8.x);
                    af[mt][2] = __float_as_uint(pr.y);
                    af[mt][3] = __float_as_uint(pr8.y);
                }
#pragma unroll
                for (int nt = 0; nt < 4; nt++) {
                    const int nb = (wn + nt * 8 + r0) * 18 + ks * 4 + c4;
                    const float2 bv = Bs2[nb];
                    bf[nt][0] = __float_as_uint(bv.x);
                    bf[nt][1] = __float_as_uint(bv.y);
                }
#pragma unroll
                for (int mt = 0; mt < 4; mt++)
#pragma unroll
                    for (int nt = 0; nt < 4; nt++)
                        mma_tf32(acc[mt][nt], af[mt], bf[nt]);
            }
        }
    }

    // epilogue
    if (!active) return;
#pragma unroll
    for (int mt = 0; mt < 4; mt++) {
#pragma unroll
        for (int half = 0; half < 2; half++) {
            const int lr = wm + mt * 16 + r0 + half * 8;
            if (m0 + lr >= cnt) continue;
            const int row = slist[lr];
#pragma unroll
            for (int nt = 0; nt < 4; nt++) {
                const int col = wn + nt * 8 + c4 * 2;
                const float a0 = acc[mt][nt][half * 2 + 0];
                const float a1 = acc[mt][nt][half * 2 + 1];
                if (isq) {
                    float2 v = { a0 + Wq_b[col], a1 + Wq_b[col + 1] };
                    *(float2*)(g_Cq + (size_t)row * HID + col) = v;
                } else if (col < 64) {
                    float2 v = { a0 + Wk_b[job * 64 + col], a1 + Wk_b[job * 64 + col + 1] };
                    *(float2*)(g_Ck + (size_t)row * NKV + job * 64 + col) = v;
                } else {
                    const int c = col - 64;
                    float2 v = { a0 + Wv_b[job * 64 + c], a1 + Wv_b[job * 64 + c + 1] };
                    *(float2*)(g_Cv + (size_t)row * NKV + job * 64 + c) = v;
                }
            }
        }
    }
}

// ---------------- recurrence: 6-stage cp.async ring, 1 barrier/step ----------------
// thread mapping: j = tid>>2 (column), ib = tid&3; Mreg[r] = M[ib+4r][j]
#define RSTG 208   /* floats per stage: k64 | v64 | q64 | meta4 | pad */

__global__ __launch_bounds__(256) void recur_kernel(
    const float* __restrict__ M0, float* __restrict__ out_m, int write_m)
{
    const int b = blockIdx.x / NM1;
    const int s = blockIdx.x % NM1;
    const int tid = threadIdx.x;
    const int j  = tid >> 2;
    const int ib = tid & 3;

    float Mreg[16];
    const float* m0p = M0 + ((size_t)(b * NM1 + s)) * HID * HID;
#pragma unroll
    for (int r = 0; r < 16; r++) Mreg[r] = m0p[(ib + 4 * r) * HID + j];

    __shared__ float srf[6 * RSTG];
    const uint32_t sring = smem_u32(srf);

    auto load_stage = [&](int t) {
        const uint32_t st = sring + (uint32_t)(t % 6) * (RSTG * 4);
        const int m = t * BATCH + b;
        if (tid < 16)       cp16(st + tid * 16,              g_Ck + (size_t)m * NKV + s * HID + tid * 4);
        else if (tid < 32)  cp16(st + 256 + (tid - 16) * 16, g_Cv + (size_t)m * NKV + s * HID + (tid - 16) * 4);
        else if (tid < 48)  cp16(st + 512 + (tid - 32) * 16, g_Cq + (size_t)m * HID + (tid - 32) * 4);
        else if (tid == 48) cp16(st + 768,                   &g_meta[m]);
    };

#pragma unroll
    for (int t = 0; t < 5; t++) { load_stage(t); cp_commit(); }

    for (int t = 0; t < SEQ; t++) {
        cp_wait<4>();
        __syncthreads();
        if (t + 5 < SEQ) load_stage(t + 5);
        cp_commit();

        const float* st = srf + (t % 6) * RSTG;
        const int* sti = (const int*)st;
        const int i0 = sti[192], i1 = sti[193];
        const float gg0 = st[194], gg1 = st[195];

        float cf = 0.f, w = 0.f;
        if (s == 0)  { cf += 1.f; w += 1.f; }
        if (s == i0) { cf += 1.f; w += gg0; }
        if (s == i1) { cf += 1.f; w += gg1; }

        const float vj = st[64 + j];
        if (cf != 0.f) {
            const float cv = cf * vj;
#pragma unroll
            for (int r = 0; r < 16; r++)
                Mreg[r] = fmaf(st[ib + 4 * r], cv, Mreg[r]);
        }

        float p0 = 0.f, p1 = 0.f;
#pragma unroll
        for (int r = 0; r < 8; r++) {
            p0 = fmaf(st[128 + ib + 8 * r],     Mreg[2 * r],     p0);
            p1 = fmaf(st[128 + ib + 8 * r + 4], Mreg[2 * r + 1], p1);
        }
        float p = p0 + p1;
        p += __shfl_xor_sync(0xffffffffu, p, 1);
        p += __shfl_xor_sync(0xffffffffu, p, 2);

        if (ib == 0) {
            const int row = t * BATCH + b;
            const int pos = (s == 0) ? 0 : (s == i0) ? 1 : (s == i1) ? 2 : -1;
            if (pos >= 0) g_c3[((size_t)row * 3 + pos) * HID + j] = w * p;
            if (s == 0) {
                if (i0 == 0) g_c3[((size_t)row * 3 + 1) * HID + j] = 0.f;
                if (i1 == 0) g_c3[((size_t)row * 3 + 2) * HID + j] = 0.f;
            }
        }
    }

    if (write_m) {
        float* mo = out_m + ((size_t)(b * NM1 + s)) * HID * HID;
#pragma unroll
        for (int r = 0; r < 16; r++) mo[(ib + 4 * r) * HID + j] = Mreg[r];
    }
}

// ---------------- finalize: o[t,b,j] = sum of 3 compact contribs ----------------
__global__ __launch_bounds__(256) void finalize_kernel(float* __restrict__ out)
{
    const int idx = blockIdx.x * 256 + threadIdx.x;
    const int tb = idx >> 6, j = idx & 63;
    out[idx] = g_c3[((size_t)tb * 3 + 0) * HID + j]
             + g_c3[((size_t)tb * 3 + 1) * HID + j]
             + g_c3[((size_t)tb * 3 + 2) * HID + j];
}

// ---------------- launch ----------------
extern "C" void kernel_launch(void* const* d_in, const int* in_sizes, int n_in,
                              void* d_out, int out_size)
{
    const float* X    = (const float*)d_in[0];
    const float* M0   = (const float*)d_in[1];
    const float* Wk_w = (const float*)d_in[2];
    const float* Wk_b = (const float*)d_in[3];
    const float* Wv_w = (const float*)d_in[4];
    const float* Wv_b = (const float*)d_in[5];
    const float* Wg_w = (const float*)d_in[6];
    const float* Wg_b = (const float*)d_in[7];
    const float* Wq_w = (const float*)d_in[8];
    const float* Wq_b = (const float*)d_in[9];
    float* out = (float*)d_out;

    // launch 0: fused gate + weight prep (+ g_cnt zero)
    gate_prep<<<GATE_BLKS + WPREP_BLKS, 256>>>(X, Wg_w, Wg_b, Wk_w, Wv_w, Wq_w);
    // launch 1
    listbuild<<<ROWS / 256, 256>>>();
    // launch 2
    cudaFuncSetAttribute(gemm_mma, cudaFuncAttributeMaxDynamicSharedMemorySize, GSMEM);
    gemm_mma<<<dim3(64, 9), 256, GSMEM>>>(Wk_b, Wv_b, Wq_b);

    const long OUTSEQ = (long)SEQ * BATCH * HID;            // 524288
    const long MTOT   = (long)BATCH * NM1 * HID * HID;      // 1179648
    const int write_m = ((long)out_size >= OUTSEQ + MTOT) ? 1 : 0;

    // launch 3 (profiled next round)
    recur_kernel<<<BATCH * NM1, 256>>>(M0, out + OUTSEQ, write_m);
    // launch 4
    finalize_kernel<<<(int)(OUTSEQ / 256), 256>>>(out);
}